// round 17
// baseline (speedup 1.0000x reference)
#include <cuda_runtime.h>
#include <cuda_fp16.h>
#include <math.h>
#include <stdint.h>

#define BATCH 32
#define C     256
#define COUT  256
#define H     56
#define W     56
#define HW    3136

#define XWORDS 1856          // x tile: 232 pixels x 8 words, addr = 8p + 2(c&3) + (c>>2)
#define XPAD   2048
#define WWORDS 9216          // w buffer: 9 taps x (2 cb x 4 wn x 32 lanes x 32B swizzled)
#define SMEM_WORDS (2 * XPAD + 2 * WWORDS)      // 22528
#define SMEM_BYTES (SMEM_WORDS * 4)             // 90112
#define NSLOT  15

// Packed quantized fp16 weights, lane-major with 16B-chunk half-swap swizzle:
// [chunk(16)][tap(9)][cb(2)][wn(4)][64 x 16B chunks]
// Lane's 32B = chunks {(2*lane)^b, (2*lane+1)^b}, b=(lane>>2)&1.
__device__ unsigned short g_wq[16u * 9u * 256u * 16u];

// floor-to-2^-16-grid then round-to-fp16 (round_to_fixed clamps dead: |x|<<32768)
__device__ __forceinline__ uint32_t quant_pack(float a, float b) {
    float fa = (float)__float2int_rd(a * 65536.0f) * (1.0f / 65536.0f);
    float fb = (float)__float2int_rd(b * 65536.0f) * (1.0f / 65536.0f);
    __half2 h = __floats2half2_rn(fa, fb);
    return *(uint32_t*)&h;
}
__device__ __forceinline__ float quant_scalar(float x) {
    return (float)__float2int_rd(x * 65536.0f) * (1.0f / 65536.0f);
}

__device__ __forceinline__ uint32_t smem_u32(const void* p) {
    uint32_t a;
    asm("{ .reg .u64 t; cvta.to.shared.u64 t, %1; cvt.u32.u64 %0, t; }" : "=r"(a) : "l"(p));
    return a;
}
#define CP_ASYNC16(dst, src) \
    asm volatile("cp.async.cg.shared.global [%0], [%1], 16;" :: "r"(dst), "l"(src))
#define CP_COMMIT()  asm volatile("cp.async.commit_group;" ::: "memory")
#define CP_WAIT0()   asm volatile("cp.async.wait_group 0;" ::: "memory")

// ---------------- weight pre-quantization / packing (unchanged from R16) ----------------
__global__ void quant_weights_kernel(const float* __restrict__ shiftp,
                                     const float* __restrict__ signp)
{
    int gid = blockIdx.x * blockDim.x + threadIdx.x;   // [cout][ci][tap]
    int cout = gid / (C * 9);
    int rem  = gid - cout * (C * 9);
    int ci   = rem / 9;
    int tap  = rem - ci * 9;

    float sr = rintf(fminf(fmaxf(shiftp[gid], -14.0f), 0.0f));
    float g  = rintf(signp[gid]);
    float sg = (g > 0.0f) ? 1.0f : ((g < 0.0f) ? -1.0f : 0.0f);
    float wf = ldexpf(sg, (int)sr);
    __half h = __float2half(wf);                       // exact

    int chunk = ci >> 4;
    int l     = ci & 15;
    int half  = l >> 3;
    int qc    = (l & 7) >> 1;
    int pos   = l & 1;

    int cb = cout >> 7;
    int r  = cout & 127;
    int wn = r >> 5;
    int nn = (r >> 3) & 3;
    int qr = r & 7;

    int lane  = qr * 4 + qc;
    int b     = (lane >> 2) & 1;
    int cidx  = (2 * lane + (nn >> 1)) ^ b;
    int word  = cidx * 4 + (nn & 1) * 2 + half;
    size_t wd = ((size_t)(chunk * 9 + tap) * 2048) + cb * 1024 + wn * 256 + word;
    g_wq[wd * 2 + pos] = __half_as_ushort(h);
}

// ---------------- main MMA conv ----------------
// CTA: M=112 (2 rows), N=128. 8 warps = 2(M) x 4(N).
// MTS=4 warps: pure cp.async+MMA. MTS=3 warps (128 thr) own all x staging.
// A fragments: k-half-interleaved x layout -> 2x LDS.64 per (tap,mt)
// replaces 4x LDS.32 (same wavefronts, half the instructions/scoreboards).
// B fragments: 2x LDS.128 per tap (R16 swizzle). One barrier/chunk, unroll-2.

template<int MTS, int NS>
__device__ __forceinline__ void conv_body(
    const float* __restrict__ in_b,
    const float* __restrict__ biasp,
    float* __restrict__ out_b,
    uint32_t* __restrict__ smem,
    int oh_base, int cout0, int tid, int wn, int mt0)
{
    uint32_t* const sx0 = smem;
    uint32_t* const sx1 = smem + XPAD;
    uint32_t* const sw0 = smem + 2 * XPAD;
    uint32_t* const sw1 = smem + 2 * XPAD + WWORDS;
    const uint32_t sw0a = smem_u32(sw0), sw1a = smem_u32(sw1);

    const int lane = tid & 31;
    const int qc = lane & 3;
    const int qr = lane >> 2;
    const int bsw = (lane >> 2) & 1;
    const int wl0 = wn * 256 + (((2 * lane)     ^ bsw) << 2);
    const int wl1 = wn * 256 + (((2 * lane + 1) ^ bsw) << 2);

    // A-fragment base word offsets (k-half pair adjacent): 8*pixel + 2*qc
    int aoffA[MTS], aoffB[MTS];
#pragma unroll
    for (int mt = 0; mt < MTS; ++mt) {
        int mA = (mt0 + mt) * 16 + qr;
        int mB = mA + 8;
        int pA = (mA / 56) * 58 + (mA % 56);
        int pB = (mB / 56) * 58 + (mB % 56);
        aoffA[mt] = 8 * pA + 2 * qc;
        aoffB[mt] = 8 * pB + 2 * qc;
    }

    float acc[MTS][4][4];
#pragma unroll
    for (int mt = 0; mt < MTS; ++mt)
#pragma unroll
        for (int nn = 0; nn < 4; ++nn)
#pragma unroll
            for (int r = 0; r < 4; ++r) acc[mt][nn][r] = 0.0f;

    const char* wsrc_base = (const char*)g_wq + ((size_t)cout0 * 32);

    // ---- staging geometry: NS slots, 128 threads (wm=1 group only) ----
    // slot word w = sbase + it*128; p = w>>3; k = w&7; c = (k>>1) + 4*(k&1)
    int  xoff[NS > 0 ? NS : 1];
    bool xval[NS > 0 ? NS : 1];
    const int sbase = wn * 32 + lane;
    if (NS > 0) {
#pragma unroll
        for (int it = 0; it < NS; ++it) {
            int w   = sbase + it * 128;
            int p   = w >> 3;
            int k   = w & 7;
            int c   = (k >> 1) + ((k & 1) << 2);
            int row = p / 58;
            int col = p - row * 58;
            int ih  = oh_base + row - 1;
            int iw  = col - 1;
            xval[it] = (w < XWORDS) && (ih >= 0) && (ih < H) && (iw >= 0) && (iw < W);
            xoff[it] = 2 * c * HW + ih * W + iw;
        }
#pragma unroll
        for (int it = 0; it < NS; ++it) {
            int w = sbase + it * 128;
            if (w < XWORDS) {
                float v0 = 0.0f, v1 = 0.0f;
                if (xval[it]) {
                    const float* p = in_b + xoff[it];
                    v0 = __ldg(p); v1 = __ldg(p + HW);
                }
                sx0[w] = quant_pack(v0, v1);
            }
        }
    }
#pragma unroll
    for (int tap = 0; tap < 9; ++tap)
        CP_ASYNC16(sw0a + tap * 4096 + tid * 16,
                   wsrc_base + (size_t)tap * 8192 + tid * 16);
    CP_COMMIT();

#pragma unroll 2
    for (int chunk = 0; chunk < 16; ++chunk) {
        const int cur = chunk & 1;                 // compile-time after unroll-2
        uint32_t* const xc = cur ? sx1 : sx0;
        uint32_t* const xn = cur ? sx0 : sx1;
        const uint32_t* wc = cur ? sw1 : sw0;
        const uint32_t wna = cur ? sw0a : sw1a;
        const bool hasnext = (chunk < 15);

        CP_WAIT0();
        __syncthreads();   // cur buffers ready; nxt buffers free

        float pv0[NS > 0 ? NS : 1], pv1[NS > 0 ? NS : 1];
        if (NS > 0 && hasnext) {
            const float* inc_n = in_b + (size_t)(chunk + 1) * 16 * HW;
#pragma unroll
            for (int it = 0; it < NS; ++it) {
                pv0[it] = 0.0f; pv1[it] = 0.0f;
                if (xval[it]) {
                    const float* p = inc_n + xoff[it];
                    pv0[it] = __ldg(p); pv1[it] = __ldg(p + HW);
                }
            }
        }
        if (hasnext) {
            const char* wsrc = wsrc_base + (size_t)(chunk + 1) * 9 * 8192;
#pragma unroll
            for (int tap = 0; tap < 9; ++tap)
                CP_ASYNC16(wna + tap * 4096 + tid * 16,
                           wsrc + (size_t)tap * 8192 + tid * 16);
            CP_COMMIT();
        }

        // ---- pure MMA tap loop ----
#pragma unroll
        for (int tap = 0; tap < 9; ++tap) {
            const int kh = tap / 3, kw = tap - kh * 3;
            const int tdelta = (kh * 58 + kw) * 8;

            uint4 wA4 = *(const uint4*)&wc[tap * 1024 + wl0];
            uint4 wB4 = *(const uint4*)&wc[tap * 1024 + wl1];
            const uint32_t b0[4] = { wA4.x, wA4.z, wB4.x, wB4.z };
            const uint32_t b1[4] = { wA4.y, wA4.w, wB4.y, wB4.w };

#pragma unroll
            for (int mt = 0; mt < MTS; ++mt) {
                uint2 aA = *(const uint2*)&xc[aoffA[mt] + tdelta];  // (a0, a2)
                uint2 aB = *(const uint2*)&xc[aoffB[mt] + tdelta];  // (a1, a3)
#pragma unroll
                for (int nn = 0; nn < 4; ++nn) {
                    asm volatile(
                        "mma.sync.aligned.m16n8k16.row.col.f32.f16.f16.f32 "
                        "{%0,%1,%2,%3}, {%4,%5,%6,%7}, {%8,%9}, {%0,%1,%2,%3};\n"
                        : "+f"(acc[mt][nn][0]), "+f"(acc[mt][nn][1]),
                          "+f"(acc[mt][nn][2]), "+f"(acc[mt][nn][3])
                        : "r"(aA.x), "r"(aB.x), "r"(aA.y), "r"(aB.y),
                          "r"(b0[nn]), "r"(b1[nn]));
                }
            }
        }

        // STS next x — hazards covered by next top barrier
        if (NS > 0 && hasnext) {
#pragma unroll
            for (int it = 0; it < NS; ++it) {
                int w = sbase + it * 128;
                if (w < XWORDS)
                    xn[w] = quant_pack(pv0[it], pv1[it]);
            }
        }
    }

    // ---- epilogue ----
#pragma unroll
    for (int nn = 0; nn < 4; ++nn) {
        int cl = wn * 32 + nn * 8 + 2 * qc;
        float bq0 = quant_scalar(biasp[cout0 + cl]);
        float bq1 = quant_scalar(biasp[cout0 + cl + 1]);
        float* o0 = out_b + (size_t)(cout0 + cl) * HW;
        float* o1 = o0 + HW;
#pragma unroll
        for (int mt = 0; mt < MTS; ++mt) {
            int mA = (mt0 + mt) * 16 + qr;
            int mB = mA + 8;
            int iA = (oh_base + mA / 56) * W + (mA % 56);
            int iB = (oh_base + mB / 56) * W + (mB % 56);
            o0[iA] = acc[mt][nn][0] + bq0;
            o1[iA] = acc[mt][nn][1] + bq1;
            o0[iB] = acc[mt][nn][2] + bq0;
            o1[iB] = acc[mt][nn][3] + bq1;
        }
    }
}

__global__ __launch_bounds__(256, 2)
void conv_mma_kernel(const float* __restrict__ in,
                     const float* __restrict__ biasp,
                     float* __restrict__ out)
{
    extern __shared__ uint32_t smem[];

    const int tid = threadIdx.x;
    const int w   = tid >> 5;
    const int wm  = w & 1;
    const int wn  = w >> 1;
    const int oh_base = blockIdx.x * 2;
    const int cout0   = blockIdx.y * 128;
    const int b       = blockIdx.z;

    const float* in_b  = in  + (size_t)b * C * HW;
    float*       out_b = out + (size_t)b * COUT * HW;

    if (wm == 0)
        conv_body<4, 0>(in_b, biasp, out_b, smem, oh_base, cout0, tid, wn, 0);
    else
        conv_body<3, NSLOT>(in_b, biasp, out_b, smem, oh_base, cout0, tid, wn, 4);
}

extern "C" void kernel_launch(void* const* d_in, const int* in_sizes, int n_in,
                              void* d_out, int out_size)
{
    const float* in    = (const float*)d_in[0];
    const float* shift = (const float*)d_in[1];
    const float* sign  = (const float*)d_in[2];
    const float* bias  = (const float*)d_in[3];
    float* out = (float*)d_out;

    cudaFuncSetAttribute(conv_mma_kernel,
                         cudaFuncAttributeMaxDynamicSharedMemorySize, SMEM_BYTES);

    quant_weights_kernel<<<2304, 256>>>(shift, sign);
    dim3 grid(H / 2, COUT / 128, BATCH);               // 28 x 2 x 32
    conv_mma_kernel<<<grid, 256, SMEM_BYTES>>>(in, bias, out);
}